// round 2
// baseline (speedup 1.0000x reference)
#include <cuda_runtime.h>
#include <cstdint>

// Problem constants: B=1024, T=512, I=256, H=256, 3H=768
#define Bsz  1024
#define Tsz  512
#define Isz  256
#define Hsz  256
#define Gsz  768
#define K2   512   // fused K = I + H
#define BM   8     // batch rows per CTA

// Persistent device scratch (no allocations allowed).
// g_Wt: fused transposed weights, [K2=512][G=768]:
//   rows 0..255   = W_ih^T  (k = input feature)
//   rows 256..511 = W_hh^T  (k = hidden feature)
__device__ float g_Wt[K2 * Gsz];
// g_bias: [0..255]=b_r (b_ih+b_hh), [256..511]=b_z (b_ih+b_hh),
//         [512..767]=b_ih_n, [768..1023]=b_hh_n   (n-gate biases can't merge: r multiplies hg)
__device__ float g_bias[4 * 256];

typedef unsigned long long ull;

__device__ __forceinline__ ull pack2(float x, float y) {
    ull r;
    asm("mov.b64 %0, {%1, %2};" : "=l"(r) : "f"(x), "f"(y));
    return r;
}
__device__ __forceinline__ void unpk2(ull v, float& x, float& y) {
    asm("mov.b64 {%0, %1}, %2;" : "=f"(x), "=f"(y) : "l"(v));
}
// Packed 2xFP32 FMA — sm_100+ only reachable via PTX fma.rn.f32x2 (ptxas never auto-fuses).
__device__ __forceinline__ void fma2(ull& d, ull a, ull b) {
    asm("fma.rn.f32x2 %0, %1, %2, %3;" : "=l"(d) : "l"(a), "l"(b), "l"(d));
}

__global__ void prep_kernel(const float* __restrict__ W_ih, const float* __restrict__ W_hh,
                            const float* __restrict__ b_ih, const float* __restrict__ b_hh) {
    int idx = blockIdx.x * blockDim.x + threadIdx.x;
    if (idx < K2 * Gsz) {
        int k = idx / Gsz;
        int g = idx - k * Gsz;
        g_Wt[idx] = (k < Isz) ? W_ih[g * Isz + k] : W_hh[g * Hsz + (k - Isz)];
    }
    if (idx < 256) {
        g_bias[idx]       = b_ih[idx]       + b_hh[idx];        // r
        g_bias[256 + idx] = b_ih[256 + idx] + b_hh[256 + idx];  // z
        g_bias[512 + idx] = b_ih[512 + idx];                    // xn
        g_bias[768 + idx] = b_hh[512 + idx];                    // hg
    }
}

// One persistent CTA per 8 batch rows; h lives in SMEM for all 512 steps.
// Thread c (0..255) owns hidden column c for all 8 rows. Per step, per k we do
// 48 FMA (24 FFMA2) against 6 weight scalars streamed from L2 (broadcast across CTAs).
__global__ void __launch_bounds__(256) gru_kernel(const float* __restrict__ x,
                                                  const int* __restrict__ seqlen,
                                                  float* __restrict__ out) {
    __shared__ __align__(16) float xs[Isz * BM];  // x_t staged, layout [k][b]
    __shared__ __align__(16) float hs[Hsz * BM];  // h,      layout [k][b]

    const int c  = threadIdx.x;
    const int b0 = blockIdx.x * BM;
    const float* xb = x + (long long)b0 * Tsz * Isz;

    int   L[BM];
    float hn[BM];
#pragma unroll
    for (int b = 0; b < BM; b++) {
        L[b]  = seqlen[b0 + b];
        hn[b] = 0.0f;
        hs[c * BM + b] = 0.0f;
    }
    const float br  = g_bias[c];
    const float bz  = g_bias[256 + c];
    const float bxn = g_bias[512 + c];
    const float bhg = g_bias[768 + c];
    const float* __restrict__ Wc = g_Wt + c;
    __syncthreads();

    for (int t = 0; t < Tsz; t++) {
        // stage x_t rows (coalesced: 128B per warp per row)
#pragma unroll
        for (int b = 0; b < BM; b++)
            xs[c * BM + b] = xb[(long long)b * (Tsz * Isz) + t * Isz + c];
        __syncthreads();

        ull aR[4], aZ[4], aXN[4], aHG[4];
#pragma unroll
        for (int p = 0; p < 4; p++) {
            aR[p]  = pack2(br, br);
            aZ[p]  = pack2(bz, bz);
            aXN[p] = pack2(bxn, bxn);
            aHG[p] = pack2(bhg, bhg);
        }

#pragma unroll 8
        for (int k = 0; k < Isz; k++) {
            // 6 weight scalars: 3 gates x (x-part row k, h-part row 256+k)
            float wxr = Wc[k * Gsz];
            float wxz = Wc[k * Gsz + 256];
            float wxn = Wc[k * Gsz + 512];
            float whr = Wc[(Isz + k) * Gsz];
            float whz = Wc[(Isz + k) * Gsz + 256];
            float whn = Wc[(Isz + k) * Gsz + 512];
            ull wxr2 = pack2(wxr, wxr), wxz2 = pack2(wxz, wxz), wxn2 = pack2(wxn, wxn);
            ull whr2 = pack2(whr, whr), whz2 = pack2(whz, whz), whn2 = pack2(whn, whn);

            // 8 batch values each for x and h, as 2x LDS.128 (same-address broadcast)
            ulonglong2 xv0 = *reinterpret_cast<const ulonglong2*>(&xs[k * BM]);
            ulonglong2 xv1 = *reinterpret_cast<const ulonglong2*>(&xs[k * BM + 4]);
            ulonglong2 hv0 = *reinterpret_cast<const ulonglong2*>(&hs[k * BM]);
            ulonglong2 hv1 = *reinterpret_cast<const ulonglong2*>(&hs[k * BM + 4]);
            ull xp[4] = {xv0.x, xv0.y, xv1.x, xv1.y};
            ull hp[4] = {hv0.x, hv0.y, hv1.x, hv1.y};
#pragma unroll
            for (int p = 0; p < 4; p++) {
                fma2(aR[p],  xp[p], wxr2);
                fma2(aZ[p],  xp[p], wxz2);
                fma2(aXN[p], xp[p], wxn2);
                fma2(aR[p],  hp[p], whr2);
                fma2(aZ[p],  hp[p], whz2);
                fma2(aHG[p], hp[p], whn2);
            }
        }
        __syncthreads();  // all reads of hs done before we overwrite it

#pragma unroll
        for (int p = 0; p < 4; p++) {
            float rv0, rv1, zv0, zv1, xn0, xn1, hg0, hg1;
            unpk2(aR[p],  rv0, rv1);
            unpk2(aZ[p],  zv0, zv1);
            unpk2(aXN[p], xn0, xn1);
            unpk2(aHG[p], hg0, hg1);
            float rvv[2] = {rv0, rv1}, zvv[2] = {zv0, zv1};
            float xnn[2] = {xn0, xn1}, hgg[2] = {hg0, hg1};
#pragma unroll
            for (int e = 0; e < 2; e++) {
                int b = 2 * p + e;
                float r = 1.0f / (1.0f + expf(-rvv[e]));
                float z = 1.0f / (1.0f + expf(-zvv[e]));
                float n = tanhf(xnn[e] + r * hgg[e]);
                float hold = hs[c * BM + b];
                float hnew = (1.0f - z) * n + z * hold;
                hs[c * BM + b] = hnew;
                if (t + 1 == L[b]) hn[b] = hnew;  // last observed step for this row
            }
        }
        __syncthreads();  // hnew visible before next step's k-loop
    }

#pragma unroll
    for (int b = 0; b < BM; b++)
        out[(b0 + b) * Hsz + c] = hn[b];  // covers L==0 rows with 0 as well
}

extern "C" void kernel_launch(void* const* d_in, const int* in_sizes, int n_in,
                              void* d_out, int out_size) {
    const float* x       = (const float*)d_in[0];  // [B,T,I]
    const int*   seqlen  = (const int*)d_in[1];    // [B]
    const float* W_ih    = (const float*)d_in[2];  // [3H,I]
    const float* W_hh    = (const float*)d_in[3];  // [3H,H]
    const float* b_ih    = (const float*)d_in[4];  // [3H]
    const float* b_hh    = (const float*)d_in[5];  // [3H]
    float*       out     = (float*)d_out;          // [B,H]

    prep_kernel<<<(K2 * Gsz + 255) / 256, 256>>>(W_ih, W_hh, b_ih, b_hh);
    gru_kernel<<<Bsz / BM, 256>>>(x, seqlen, out);
}